// round 3
// baseline (speedup 1.0000x reference)
#include <cuda_runtime.h>

#define BATCH    4096
#define IN_FEAT  4096
#define NPAIRS_TOTAL 767   // 256 + 255 + 256

typedef unsigned long long ull;

// ---------------- scratch (device globals; no allocation allowed) ----------------
__device__ float g_h[(size_t)BATCH * IN_FEAT];        // 64 MB intermediate h
__device__ float g_gred[(size_t)NPAIRS_TOTAL * 1024]; // per (layer,pair): G1[512] | G2[512]

// ---------------- packed f32x2 helpers ----------------
__device__ __forceinline__ ull pack2(float c) {
    ull r; asm("mov.b64 %0, {%1, %1};" : "=l"(r) : "f"(c)); return r;
}
__device__ __forceinline__ ull pack2p(float lo, float hi) {
    ull r; asm("mov.b64 %0, {%1, %2};" : "=l"(r) : "f"(lo), "f"(hi)); return r;
}
__device__ __forceinline__ void fma2(ull& d, ull a, ull b) {
    asm("fma.rn.f32x2 %0, %1, %2, %3;" : "=l"(d) : "l"(a), "l"(b), "l"(d));
}
__device__ __forceinline__ float2 unpack2(ull v) {
    float2 f; asm("mov.b64 {%0, %1}, %2;" : "=f"(f.x), "=f"(f.y) : "l"(v)); return f;
}
// packed pair of warp-broadcast values (src lanes are compile-time constants)
__device__ __forceinline__ ull shfl_pair(float g, int src) {
    float lo = __shfl_sync(0xffffffffu, g, src);
    float hi = __shfl_sync(0xffffffffu, g, src + 1);
    return pack2p(lo, hi);
}

// ---------------- Prep kernel: gate reduction + permuted gather, one launch ----------------
__global__ __launch_bounds__(256) void prep_kernel(
    const float* __restrict__ g0, const float* __restrict__ g1, const float* __restrict__ g2,
    const float* __restrict__ x,  const int* __restrict__ perm)
{
    __shared__ float sG[4096];
    int tid = threadIdx.x;

    if (blockIdx.x >= NPAIRS_TOTAL) {
        // ---- gather branch: one block per batch row ----
        int b = blockIdx.x - NPAIRS_TOTAL;
        const float* xr = x + (size_t)b * IN_FEAT;
        float* hr = g_h + (size_t)b * IN_FEAT;
#pragma unroll
        for (int c = 0; c < 16; c++) {
            int q = c * 256 + tid;
            hr[q] = xr[perm[q]];
        }
        return;
    }

    // ---- gate-reduce branch ----
    int gb = blockIdx.x;
    const float* src;
    if (gb < 256)      src = g0 + (size_t)gb * 65536;          // 16*4096 floats per pair
    else if (gb < 511) src = g1 + (size_t)(gb - 256) * 65536;
    else               src = g2 + (size_t)(gb - 511) * 65536;

    float acc[16];
#pragma unroll
    for (int t = 0; t < 16; t++) acc[t] = 0.f;
#pragma unroll
    for (int rc = 0; rc < 16; rc++) {
        const float* p = src + rc * 4096;
#pragma unroll
        for (int t = 0; t < 16; t++) acc[t] += p[t * 256 + tid];
    }
#pragma unroll
    for (int t = 0; t < 16; t++) sG[t * 256 + tid] = acc[t];
    __syncthreads();

    float* dst = g_gred + (size_t)gb * 1024;
#pragma unroll
    for (int u = 0; u < 2; u++) {
        int o = u * 256 + tid;          // 0..511
        float s1 = 0.f;
#pragma unroll
        for (int n = 0; n < 8; n++) s1 += sG[o * 8 + n];
        dst[o] = s1;                     // G1[ij][m]
        int ij = o >> 3, nn = o & 7;
        float s2 = 0.f;
#pragma unroll
        for (int m = 0; m < 8; m++) s2 += sG[ij * 64 + m * 8 + nn];
        dst[512 + o] = s2;               // G2[ij][n]
    }
}

// ---------------- Layer kernel (shfl-distributed gates) ----------------
// grid = (P, 8). 128-thread blocks; each thread does RPT=4 batch rows for one
// pair k. The pair's 1024 gate floats live in warp registers (32/lane,
// lane-strided): gate flat[v] sits in lane (v & 31), reg (v >> 5). Each (i,j)
// fetches its 16 coefficients via shfl.sync with immediate source lanes,
// bypassing the SMEM crossbar (which cannot dedup broadcasts).
#define RPT 4
template<int OFFSET, bool EPI>
__global__ __launch_bounds__(128) void layer_kernel(
    int gate_base,
    const float* __restrict__ alphap,
    const float* __restrict__ scale,
    const float* __restrict__ bias,
    float* __restrict__ out)
{
    const int k = blockIdx.x;
    const int lane = threadIdx.x & 31;

    // gate registers: greg[r] = flat[r*32 + lane]  (coalesced LDG, hits L2)
    float greg[32];
    {
        const float* gp = g_gred + ((size_t)(gate_base + k)) * 1024 + lane;
#pragma unroll
        for (int r = 0; r < 32; r++) greg[r] = gp[r * 32];
    }

    const size_t col = ((size_t)(OFFSET + 2 * k)) * 8;   // 16 contiguous floats
    const int r0 = blockIdx.y * (128 * RPT) + threadIdx.x;

    float x1[RPT][8], x2[RPT][8];
#pragma unroll
    for (int rr = 0; rr < RPT; rr++) {
        const float4* hp = (const float4*)(g_h + (size_t)(r0 + rr * 128) * IN_FEAT + col);
        float4 a0 = hp[0], a1 = hp[1], b0 = hp[2], b1 = hp[3];
        x1[rr][0]=a0.x; x1[rr][1]=a0.y; x1[rr][2]=a0.z; x1[rr][3]=a0.w;
        x1[rr][4]=a1.x; x1[rr][5]=a1.y; x1[rr][6]=a1.z; x1[rr][7]=a1.w;
        x2[rr][0]=b0.x; x2[rr][1]=b0.y; x2[rr][2]=b0.z; x2[rr][3]=b0.w;
        x2[rr][4]=b1.x; x2[rr][5]=b1.y; x2[rr][6]=b1.z; x2[rr][7]=b1.w;
    }

    ull acc1[RPT][4], acc2[RPT][4];
#pragma unroll
    for (int rr = 0; rr < RPT; rr++)
#pragma unroll
        for (int t = 0; t < 4; t++) { acc1[rr][t] = 0ull; acc2[rr][t] = 0ull; }

#pragma unroll
    for (int i = 0; i < 8; i++) {
#pragma unroll
        for (int j = 0; j < 8; j++) {
            const int ij = i * 8 + j;
            const int rg = ij >> 2;          // compile-time (loop unrolled)
            const int sl = (ij & 3) * 8;     // compile-time source lane base
            float ga = greg[rg];             // holds G1[ij][0..7] across lanes sl..sl+7
            float gb = greg[16 + rg];        // holds G2[ij][0..7] likewise
            ull p0 = shfl_pair(ga, sl + 0);
            ull p1 = shfl_pair(ga, sl + 2);
            ull p2 = shfl_pair(ga, sl + 4);
            ull p3 = shfl_pair(ga, sl + 6);
            ull q0 = shfl_pair(gb, sl + 0);
            ull q1 = shfl_pair(gb, sl + 2);
            ull q2 = shfl_pair(gb, sl + 4);
            ull q3 = shfl_pair(gb, sl + 6);
#pragma unroll
            for (int rr = 0; rr < RPT; rr++) {
                ull cd = pack2(x1[rr][i] * x2[rr][j]);
                fma2(acc1[rr][0], cd, p0); fma2(acc1[rr][1], cd, p1);
                fma2(acc1[rr][2], cd, p2); fma2(acc1[rr][3], cd, p3);
                fma2(acc2[rr][0], cd, q0); fma2(acc2[rr][1], cd, q1);
                fma2(acc2[rr][2], cd, q2); fma2(acc2[rr][3], cd, q3);
            }
        }
    }

    float al = 1.f;
    float sc[16], bi[16];
    if (EPI) {
        al = __ldg(alphap);
#pragma unroll
        for (int t = 0; t < 16; t++) { sc[t] = __ldg(scale + col + t); bi[t] = __ldg(bias + col + t); }
    }

#pragma unroll
    for (int rr = 0; rr < RPT; rr++) {
        float y[16];
#pragma unroll
        for (int t = 0; t < 4; t++) {
            float2 f1 = unpack2(acc1[rr][t]); y[2 * t]     = f1.x; y[2 * t + 1]     = f1.y;
            float2 f2 = unpack2(acc2[rr][t]); y[8 + 2 * t] = f2.x; y[8 + 2 * t + 1] = f2.y;
        }
        size_t base = (size_t)(r0 + rr * 128) * IN_FEAT + col;
        if (!EPI) {
            float4* hp = (float4*)(g_h + base);
            hp[0] = make_float4(y[0], y[1], y[2], y[3]);
            hp[1] = make_float4(y[4], y[5], y[6], y[7]);
            hp[2] = make_float4(y[8], y[9], y[10], y[11]);
            hp[3] = make_float4(y[12], y[13], y[14], y[15]);
        } else {
#pragma unroll
            for (int t = 0; t < 16; t++) y[t] = al * y[t] * sc[t] + bi[t];
            float4* op = (float4*)(out + base);
            op[0] = make_float4(y[0], y[1], y[2], y[3]);
            op[1] = make_float4(y[4], y[5], y[6], y[7]);
            op[2] = make_float4(y[8], y[9], y[10], y[11]);
            op[3] = make_float4(y[12], y[13], y[14], y[15]);
        }
    }
}

// ---------------- launch ----------------
extern "C" void kernel_launch(void* const* d_in, const int* in_sizes, int n_in,
                              void* d_out, int out_size)
{
    (void)in_sizes; (void)n_in; (void)out_size;
    const float* x     = (const float*)d_in[0];
    const float* g0    = (const float*)d_in[1];
    const float* g1    = (const float*)d_in[2];
    const float* g2    = (const float*)d_in[3];
    const float* alpha = (const float*)d_in[4];
    const float* scale = (const float*)d_in[5];
    const float* bias  = (const float*)d_in[6];
    const int*   perm  = (const int*)d_in[7];
    float* out = (float*)d_out;

    prep_kernel<<<NPAIRS_TOTAL + BATCH, 256>>>(g0, g1, g2, x, perm);
    layer_kernel<0, false><<<dim3(256, 8), 128>>>(0,   nullptr, nullptr, nullptr, nullptr);
    layer_kernel<1, false><<<dim3(255, 8), 128>>>(256, nullptr, nullptr, nullptr, nullptr);
    layer_kernel<0, true ><<<dim3(256, 8), 128>>>(511, alpha, scale, bias, out);
}